// round 4
// baseline (speedup 1.0000x reference)
#include <cuda_runtime.h>
#include <math.h>

// Problem constants
#define SS        26
#define CC        80
#define CELLS     676        // 26*26
#define NB        32
#define BIMG      256
#define OBJCELLS  2028       // 3*676
#define NWORDS    (OBJCELLS/4)   // 507
#define NCH       255        // 3*(5+80)
#define DIV       16.0f      // 416/26
#define INV_IMG   (1.0f/416.0f)
#define NTHR      256
#define NSLICE    4
#define GRID      (BIMG*NSLICE)  // 1024

__constant__ float c_anchor[18] = {
    10.f,13.f, 16.f,30.f, 33.f,23.f, 30.f,61.f, 62.f,45.f,
    59.f,119.f, 116.f,90.f, 156.f,198.f, 373.f,326.f
};

__device__ float g_partial[GRID];
__device__ unsigned int g_done_count = 0;

__global__ void __launch_bounds__(NTHR)
yolo_uniform_kernel(const float* __restrict__ bx,
                    const float* __restrict__ bbox,
                    const int*   __restrict__ bidx,
                    float* __restrict__ out)
{
    const int blk  = blockIdx.x;
    const int b    = blk >> 2;       // image
    const int s    = blk & 3;        // slice within image
    const int tid  = threadIdx.x;
    const int warp = tid >> 5;
    const int lane = tid & 31;
    const float* __restrict__ x = bx + (size_t)b * NCH * CELLS;

    __shared__ int   s_base[NB];
    __shared__ int   s_o[NB];
    __shared__ int   s_cls[NB];
    __shared__ int   s_nidx[NB];
    __shared__ float s_ax[NB];
    __shared__ float s_ay[NB];
    __shared__ float s_w[NB];
    __shared__ float s_h[NB];
    __shared__ unsigned int cleared32[NWORDS];   // byte flags packed 4/word
    __shared__ float sredA[8];
    __shared__ float sredN[8];
    __shared__ int   sredC[8];
    __shared__ int   s_last;

    unsigned char* cleared = (unsigned char*)cleared32;

    for (int j = tid; j < NWORDS; j += NTHR) cleared32[j] = 0u;
    __syncthreads();

    // Phase 1: box geometry (no x access), one thread per box
    if (tid < NB) {
        const int i = tid;
        const float* bp = bbox + ((size_t)b * NB + i) * 5;
        float cls = bp[0], cx = bp[1], cy = bp[2], w = bp[3], h = bp[4];
        int nidx = bidx[b * NB + i];
        int now  = nidx - 3;
        int base = now * 85;
        int ix = (int)(cx / DIV);
        int iy = (int)(cy / DIV);
        int o = ix * SS + iy;

        s_base[i] = base;
        s_o[i]    = o;
        s_cls[i]  = (int)cls;
        s_nidx[i] = nidx;
        s_ax[i]   = (cx - (float)ix * DIV) / DIV;
        s_ay[i]   = (cy - (float)iy * DIV) / DIV;
        s_w[i]    = w;
        s_h[i]    = h;
        cleared[now * CELLS + o] = 1;   // racy duplicate writes of 1 -> benign
    }
    __syncthreads();

    // Phase 2: each warp owns exactly one box: bi = s*8 + warp  (4 slices x 8 warps = 32)
    const int bi   = s * 8 + warp;
    const int base = s_base[bi];
    const int o    = s_o[bi];
    const int cls  = s_cls[bi];
    const float* __restrict__ p = x + (size_t)base * CELLS + o;

    float acc  = 0.0f;
    float lacc = 0.0f;

    // 80 label gathers, warp-UNIFORM address -> 1 wavefront each at ~1 cyc/wf
    const float* __restrict__ pl = p + 5 * CELLS;
    #pragma unroll 16
    for (int c = 0; c < CC; c++) {
        float v = __ldg(pl + (size_t)c * CELLS);
        float hot = (c == cls) ? 1.0f : 0.0f;
        float d = v - hot;
        if (lane == (c & 31)) lacc += d * d;
    }
    acc = lacc * (1.0f / (NB * CC));

    // Head gathers (uniform) + coord/obj loss, finished on lane 0
    {
        float obj_pred = __ldg(p + 0 * CELLS);
        float rax      = __ldg(p + 1 * CELLS);
        float ray      = __ldg(p + 2 * CELLS);
        float t3       = __ldg(p + 3 * CELLS);
        float t4       = __ldg(p + 4 * CELLS);

        if (lane == 0) {
            int   nidx = s_nidx[bi];
            float ax = s_ax[bi], ay = s_ay[bi];
            float w  = s_w[bi],  h  = s_h[bi];

            float sig3 = 1.0f / (1.0f + __expf(-t3));
            float sig4 = 1.0f / (1.0f + __expf(-t4));
            float rw = c_anchor[nidx * 2 + 0] * __expf(4.0f * sig3 - 2.0f);
            float rh = c_anchor[nidx * 2 + 1] * __expf(4.0f * sig4 - 2.0f);

            // IOU with the reference's +1 offsets
            float b1x0 = rax * DIV - rw * 0.5f, b1y0 = ray * DIV - rh * 0.5f;
            float b1x1 = rax * DIV + rw * 0.5f, b1y1 = ray * DIV + rh * 0.5f;
            float b2x0 = ax  * DIV - w  * 0.5f, b2y0 = ay  * DIV - h  * 0.5f;
            float b2x1 = ax  * DIV + w  * 0.5f, b2y1 = ay  * DIV + h  * 0.5f;

            float A  = (b1x1 - b1x0 + 1.0f) * (b1y1 - b1y0 + 1.0f);
            float Bt = (b2x1 - b2x0 + 1.0f) * (b2y1 - b2y0 + 1.0f);
            float CM = (fminf(b1x1, b2x1) - fmaxf(b1x0, b2x0) + 1.0f)
                     * (fminf(b1y1, b2y1) - fmaxf(b1y0, b2y0) + 1.0f);
            float iou = CM / (A + Bt - CM);
            iou = (iou < 0.0f) ? 0.0f : iou;

            float d0 = obj_pred - iou;
            float d1 = rax - ax;
            float d2 = ray - ay;
            float d3 = (rw - w) * INV_IMG;
            float d4 = (rh - h) * INV_IMG;

            acc += 5.0f * (d0*d0 + d1*d1 + d2*d2 + d3*d3 + d4*d4) * (1.0f / NB);
        }
    }

    // No-object term: this slice handles 1/4 of the 507 float4 words (coalesced)
    float no = 0.0f;
    {
        int j4 = tid * NSLICE + s;          // each thread <= 1 word
        if (j4 < NWORDS) {
            int r    = j4 / (CELLS / 4);
            int rem4 = j4 - r * (CELLS / 4);
            const float4 v = *(const float4*)(x + (size_t)(r * 85) * CELLS + rem4 * 4);
            unsigned int m = cleared32[j4];
            if (!(m & 0x000000FFu)) no += v.x * v.x;
            if (!(m & 0x0000FF00u)) no += v.y * v.y;
            if (!(m & 0x00FF0000u)) no += v.z * v.z;
            if (!(m & 0xFF000000u)) no += v.w * v.w;
        }
    }

    // Dedup count (identical across slices, each computes its own)
    int ccount = 0;
    for (int j = tid; j < NWORDS; j += NTHR) ccount += __popc(cleared32[j]);

    // Warp shuffle reduction (fixed order -> deterministic)
    #pragma unroll
    for (int off = 16; off > 0; off >>= 1) {
        acc    += __shfl_down_sync(0xFFFFFFFFu, acc,    off);
        no     += __shfl_down_sync(0xFFFFFFFFu, no,     off);
        ccount += __shfl_down_sync(0xFFFFFFFFu, ccount, off);
    }
    if (lane == 0) { sredA[warp] = acc; sredN[warp] = no; sredC[warp] = ccount; }
    __syncthreads();

    if (tid == 0) {
        float A = 0.0f, Nn = 0.0f;
        int   Cc = 0;
        #pragma unroll
        for (int w = 0; w < 8; w++) { A += sredA[w]; Nn += sredN[w]; Cc += sredC[w]; }
        float cnt = (float)(OBJCELLS - Cc);
        g_partial[blk] = A + 0.5f * Nn / cnt;
        __threadfence();
        unsigned int old = atomicAdd(&g_done_count, 1u);
        s_last = (old == GRID - 1) ? 1 : 0;
    }
    __syncthreads();

    // Last block standing: deterministic fixed-order final reduction of 1024 partials
    if (s_last) {
        float v = g_partial[tid]
                + g_partial[tid + 256]
                + g_partial[tid + 512]
                + g_partial[tid + 768];
        #pragma unroll
        for (int off = 16; off > 0; off >>= 1)
            v += __shfl_down_sync(0xFFFFFFFFu, v, off);
        if (lane == 0) sredA[warp] = v;
        __syncthreads();
        if (tid == 0) {
            float t = 0.0f;
            #pragma unroll
            for (int w = 0; w < 8; w++) t += sredA[w];
            out[0] = t;
            atomicExch(&g_done_count, 0u);   // reset for next graph replay
        }
    }
}

extern "C" void kernel_launch(void* const* d_in, const int* in_sizes, int n_in,
                              void* d_out, int out_size)
{
    const float* bx   = (const float*)d_in[0];
    const float* bbox = (const float*)d_in[1];
    const int*   bidx = (const int*)d_in[2];
    float* out = (float*)d_out;

    yolo_uniform_kernel<<<GRID, NTHR>>>(bx, bbox, bidx, out);
}

// round 6
// speedup vs baseline: 1.5224x; 1.5224x over previous
#include <cuda_runtime.h>
#include <math.h>

// Problem constants
#define SS        26
#define CC        80
#define CELLS     676        // 26*26
#define NB        32
#define BIMG      256
#define OBJCELLS  2028       // 3*676
#define NCH       255        // 3*(5+80)
#define DIV       16.0f      // 416/26
#define INV_IMG   (1.0f/416.0f)
#define NTHR      512

__constant__ float c_anchor[18] = {
    10.f,13.f, 16.f,30.f, 33.f,23.f, 30.f,61.f, 62.f,45.f,
    59.f,119.f, 116.f,90.f, 156.f,198.f, 373.f,326.f
};

__device__ float g_img_loss[BIMG];
__device__ unsigned int g_done_count = 0;

// L2 evict_last via cache-policy register (the form ptxas accepts on sm_103)
__device__ __forceinline__ unsigned long long mk_policy() {
    unsigned long long pol;
    asm volatile("createpolicy.fractional.L2::evict_last.b64 %0, 1.0;" : "=l"(pol));
    return pol;
}
__device__ __forceinline__ float ldg_el(const float* p, unsigned long long pol) {
    float v;
    asm volatile("ld.global.nc.L2::cache_hint.f32 %0, [%1], %2;"
                 : "=f"(v) : "l"(p), "l"(pol));
    return v;
}
__device__ __forceinline__ float4 ldg_el4(const float* p, unsigned long long pol) {
    float4 v;
    asm volatile("ld.global.nc.L2::cache_hint.v4.f32 {%0,%1,%2,%3}, [%4], %5;"
                 : "=f"(v.x), "=f"(v.y), "=f"(v.z), "=f"(v.w) : "l"(p), "l"(pol));
    return v;
}

__global__ void __launch_bounds__(NTHR)
yolo_fused_kernel(const float* __restrict__ bx,
                  const float* __restrict__ bbox,
                  const int*   __restrict__ bidx,
                  float* __restrict__ out)
{
    const int b   = blockIdx.x;
    const int tid = threadIdx.x;
    const float* __restrict__ x = bx + (size_t)b * NCH * CELLS;
    const unsigned long long pol = mk_policy();

    __shared__ int   s_base[NB];   // channel base (0/85/170)
    __shared__ int   s_o[NB];      // ix*26+iy
    __shared__ int   s_cls[NB];
    __shared__ float s_lossA[NB];
    __shared__ unsigned int cleared32[OBJCELLS / 4];   // 507 words, byte flags
    __shared__ float redA[NTHR];
    __shared__ float redN[NTHR];
    __shared__ int   redC[NTHR];
    __shared__ int   s_last;

    unsigned char* cleared = (unsigned char*)cleared32;

    for (int j = tid; j < OBJCELLS / 4; j += NTHR) cleared32[j] = 0u;
    __syncthreads();

    if (tid < NB) {
        const int i = tid;
        const float* bp = bbox + ((size_t)b * NB + i) * 5;
        float cls = bp[0], cx = bp[1], cy = bp[2], w = bp[3], h = bp[4];
        int nidx = bidx[b * NB + i];
        int now  = nidx - 3;
        int base = now * 85;
        int ix = (int)(cx / DIV);
        int iy = (int)(cy / DIV);
        float ax = (cx - (float)ix * DIV) / DIV;
        float ay = (cy - (float)iy * DIV) / DIV;
        int o = ix * SS + iy;

        const float* p = x + (size_t)base * CELLS + o;
        float obj_pred = ldg_el(p + 0 * CELLS, pol);
        float rax      = ldg_el(p + 1 * CELLS, pol);
        float ray      = ldg_el(p + 2 * CELLS, pol);
        float t3       = ldg_el(p + 3 * CELLS, pol);
        float t4       = ldg_el(p + 4 * CELLS, pol);

        float sig3 = 1.0f / (1.0f + expf(-t3));
        float sig4 = 1.0f / (1.0f + expf(-t4));
        float rw = c_anchor[nidx * 2 + 0] * expf(4.0f * sig3 - 2.0f);
        float rh = c_anchor[nidx * 2 + 1] * expf(4.0f * sig4 - 2.0f);

        // IOU with the reference's +1 offsets
        float b1x0 = rax * DIV - rw * 0.5f, b1y0 = ray * DIV - rh * 0.5f;
        float b1x1 = rax * DIV + rw * 0.5f, b1y1 = ray * DIV + rh * 0.5f;
        float b2x0 = ax  * DIV - w  * 0.5f, b2y0 = ay  * DIV - h  * 0.5f;
        float b2x1 = ax  * DIV + w  * 0.5f, b2y1 = ay  * DIV + h  * 0.5f;

        float A  = (b1x1 - b1x0 + 1.0f) * (b1y1 - b1y0 + 1.0f);
        float Bt = (b2x1 - b2x0 + 1.0f) * (b2y1 - b2y0 + 1.0f);
        float CM = (fminf(b1x1, b2x1) - fmaxf(b1x0, b2x0) + 1.0f)
                 * (fminf(b1y1, b2y1) - fmaxf(b1y0, b2y0) + 1.0f);
        float iou = CM / (A + Bt - CM);
        iou = (iou < 0.0f) ? 0.0f : iou;

        float d0 = obj_pred - iou;
        float d1 = rax - ax;
        float d2 = ray - ay;
        float d3 = (rw - w) * INV_IMG;
        float d4 = (rh - h) * INV_IMG;

        s_lossA[i] = 5.0f * (d0*d0 + d1*d1 + d2*d2 + d3*d3 + d4*d4) * (1.0f / NB);
        s_base[i]  = base;
        s_o[i]     = o;
        s_cls[i]   = (int)cls;
        cleared[now * CELLS + o] = 1;   // racy duplicates all write 1 -> benign
    }
    __syncthreads();

    // Label MSE: 32 boxes x 80 classes of scattered gathers (5 per thread, MLP-friendly)
    float acc = 0.0f;
    #pragma unroll 5
    for (int idx = tid; idx < NB * CC; idx += NTHR) {
        int i = idx / CC;
        int c = idx - i * CC;
        float val = ldg_el(x + (size_t)(s_base[i] + 5 + c) * CELLS + s_o[i], pol);
        float hot = (c == s_cls[i]) ? 1.0f : 0.0f;
        float d = val - hot;
        acc += d * d;
    }
    acc *= (1.0f / (NB * CC));
    if (tid < NB) acc += s_lossA[tid];

    // No-object term over the 3 objectness rows: float4-vectorized, skip cleared cells
    float no = 0.0f;
    int ccount = 0;
    for (int j4 = tid; j4 < OBJCELLS / 4; j4 += NTHR) {
        int r    = j4 / (CELLS / 4);
        int rem4 = j4 - r * (CELLS / 4);
        const float4 v = ldg_el4(x + (size_t)(r * 85) * CELLS + rem4 * 4, pol);
        unsigned int m = cleared32[j4];   // 4 byte-flags, each 0 or 1
        if (!(m & 0x000000FFu)) no += v.x * v.x;
        if (!(m & 0x0000FF00u)) no += v.y * v.y;
        if (!(m & 0x00FF0000u)) no += v.z * v.z;
        if (!(m & 0xFF000000u)) no += v.w * v.w;
        ccount += __popc(m);
    }

    // Deterministic tree reduction over the block
    redA[tid] = acc;
    redN[tid] = no;
    redC[tid] = ccount;
    __syncthreads();
    for (int s = NTHR / 2; s > 0; s >>= 1) {
        if (tid < s) {
            redA[tid] += redA[tid + s];
            redN[tid] += redN[tid + s];
            redC[tid] += redC[tid + s];
        }
        __syncthreads();
    }

    if (tid == 0) {
        float cnt = (float)(OBJCELLS - redC[0]);
        g_img_loss[b] = redA[0] + 0.5f * redN[0] / cnt;
        __threadfence();
        unsigned int old = atomicAdd(&g_done_count, 1u);
        s_last = (old == BIMG - 1) ? 1 : 0;
    }
    __syncthreads();

    // Last block standing performs the deterministic final reduction
    if (s_last) {
        redA[tid] = (tid < BIMG) ? g_img_loss[tid] : 0.0f;
        __syncthreads();
        for (int s = NTHR / 2; s > 0; s >>= 1) {
            if (tid < s) redA[tid] += redA[tid + s];
            __syncthreads();
        }
        if (tid == 0) {
            out[0] = redA[0];
            atomicExch(&g_done_count, 0u);   // reset for next graph replay
        }
    }
}

extern "C" void kernel_launch(void* const* d_in, const int* in_sizes, int n_in,
                              void* d_out, int out_size)
{
    const float* bx   = (const float*)d_in[0];
    const float* bbox = (const float*)d_in[1];
    const int*   bidx = (const int*)d_in[2];
    float* out = (float*)d_out;

    yolo_fused_kernel<<<BIMG, NTHR>>>(bx, bbox, bidx, out);
}